// round 6
// baseline (speedup 1.0000x reference)
#include <cuda_runtime.h>

#define BATCH 32
#define NIN   2312
#define NHID  512
#define NOUT  10
#define TT    350
#define TKLEN 100
#define NIG   73    // ceil(NIN/32) mask words per (b,t)
#define NHG   (NHID/32)

#define THETA 10.0f
#define D_SR  0.90483741803595952f     // exp(-0.1)
#define C_SR  0.27182818284590452f     // e/10
#define E10   4.5399929762484854e-05f  // exp(-10)
#define D_REF 0.36787944117144233f     // exp(-1)
#define C_REF -54.365636569180902f     // -20e

// scratch (allocation-free: device globals)
__device__ float    g_W1T[(size_t)NIN * NHID];          // [i][h]
__device__ unsigned g_M  [(size_t)BATCH * TT * NIG];    // X bitmasks [b][t][ig]
__device__ float    g_G1 [(size_t)BATCH * TT * NHID];   // [b][t][h]
__device__ unsigned g_S1b[(size_t)BATCH * TT * NHG];    // s1 bitmasks [b][t][hg]
__device__ float    g_G2 [(size_t)BATCH * TT * NOUT];   // [b][t][o]

// ---------------------------------------------------------------------------
// Transpose W1 [NHID][NIN] -> W1T [NIN][NHID]
// ---------------------------------------------------------------------------
__global__ void __launch_bounds__(256) w1t_kernel(const float* __restrict__ W1) {
    __shared__ float tile[32][33];
    int i0 = blockIdx.x * 32;
    int h0 = blockIdx.y * 32;
    int lx = threadIdx.x & 31;
    int ly = threadIdx.x >> 5;

    #pragma unroll
    for (int r = 0; r < 4; r++) {
        int h = h0 + ly + r * 8;
        int i = i0 + lx;
        tile[ly + r * 8][lx] = (i < NIN) ? W1[(size_t)h * NIN + i] : 0.f;
    }
    __syncthreads();
    #pragma unroll
    for (int r = 0; r < 4; r++) {
        int i = i0 + ly + r * 8;
        int h = h0 + lx;
        if (i < NIN) g_W1T[(size_t)i * NHID + h] = tile[lx][ly + r * 8];
    }
}

// ---------------------------------------------------------------------------
// Mask build: block per (b, ig). Stage 32 rows of X coalescedly in smem,
// then thread t packs the 32-bit word -> g_M[b][t][ig].
// ---------------------------------------------------------------------------
__global__ void __launch_bounds__(352) maskbuild_kernel(const float* __restrict__ X) {
    __shared__ float xs[32][TT];
    const int ig = blockIdx.x;
    const int b  = blockIdx.y;
    const int tid = threadIdx.x;

    #pragma unroll 1
    for (int j = 0; j < 32; j++) {
        int i = ig * 32 + j;
        if (tid < TT)
            xs[j][tid] = (i < NIN) ? X[((size_t)b * NIN + i) * TT + tid] : 0.f;
    }
    __syncthreads();

    if (tid < TT) {
        unsigned w = 0;
        #pragma unroll
        for (int j = 0; j < 32; j++)
            if (xs[j][tid] != 0.f) w |= 1u << j;
        g_M[((size_t)b * TT + tid) * NIG + ig] = w;
    }
}

// ---------------------------------------------------------------------------
// Sparse GEMM1: warp per (b,t); 8 consecutive t per block (L1 row reuse).
// Gathers active W1T rows in ascending-i order (deterministic).
// ---------------------------------------------------------------------------
__device__ __forceinline__ void add4(float4& a, const float4& r) {
    a.x += r.x; a.y += r.y; a.z += r.z; a.w += r.w;
}

__global__ void __launch_bounds__(256) spgemm1_kernel() {
    const int warp = threadIdx.x >> 5;
    const int lane = threadIdx.x & 31;
    const int b = blockIdx.y;
    const int t = blockIdx.x * 8 + warp;
    if (t >= TT) return;

    const unsigned* __restrict__ mrow = g_M + ((size_t)b * TT + t) * NIG;

    float4 acc0 = make_float4(0.f, 0.f, 0.f, 0.f);
    float4 acc1 = acc0, acc2 = acc0, acc3 = acc0;

    #pragma unroll
    for (int cb = 0; cb < 96; cb += 32) {
        unsigned mw = (cb + lane < NIG) ? mrow[cb + lane] : 0u;
        unsigned act = __ballot_sync(0xffffffffu, mw != 0u);
        while (act) {
            int j = __ffs(act) - 1;
            act &= act - 1;
            unsigned w = __shfl_sync(0xffffffffu, mw, j);
            int ibase = (cb + j) * 32;
            while (w) {
                int bit = __ffs(w) - 1;
                w &= w - 1;
                const float4* row = (const float4*)(g_W1T + (size_t)(ibase + bit) * NHID);
                float4 r0 = row[lane];
                float4 r1 = row[lane + 32];
                float4 r2 = row[lane + 64];
                float4 r3 = row[lane + 96];
                add4(acc0, r0); add4(acc1, r1); add4(acc2, r2); add4(acc3, r3);
            }
        }
    }

    float4* out = (float4*)(g_G1 + ((size_t)b * TT + t) * NHID);
    out[lane]      = acc0;
    out[lane + 32] = acc1;
    out[lane + 64] = acc2;
    out[lane + 96] = acc3;
}

// ---------------------------------------------------------------------------
// scan1 v3: block = (b, 128-h slice), 128 threads, one channel per thread.
// gv stream: double-buffered 14-deep register prefetch (hides L2 latency).
// gd stream (t-100): per-thread smem delay line ring[t&127][tid] — each
// thread touches only its own column -> NO block syncs anywhere.
// Emits spike bitmasks via ballot. Per-channel arithmetic identical.
// ---------------------------------------------------------------------------
#define SCH 14   // chunk length; 25*14 = 350 exactly

__global__ void __launch_bounds__(128) scan1_kernel() {
    __shared__ float ring[128][128];   // 64 KB: [t mod 128][channel]

    const int b   = blockIdx.y;
    const int h0  = blockIdx.x * 128;
    const int tid = threadIdx.x;
    const int lane = tid & 31;
    const int hg  = (h0 + tid) >> 5;

    const float* __restrict__ g = g_G1 + (size_t)b * TT * NHID + h0 + tid;
    unsigned* __restrict__ sb = g_S1b + (size_t)b * TT * NHG + hg;

    float pa = 0.f, pb = 0.f;
    float qa = 0.f, qb = 0.f;
    float ra = 0.f, rb = 0.f;

    float bufA[SCH], bufB[SCH];

    // preload chunk 0
    #pragma unroll
    for (int tt = 0; tt < SCH; tt++)
        bufA[tt] = __ldg(&g[(size_t)tt * NHID]);

    #pragma unroll 1
    for (int c = 0; c < 26; c += 2) {
        // ---- even chunk: compute from bufA, prefetch into bufB ----
        {
            const int tn0 = (c + 1) * SCH;
            #pragma unroll
            for (int tt = 0; tt < SCH; tt++) {
                int tn = tn0 + tt;
                bufB[tt] = (tn < TT) ? __ldg(&g[(size_t)tn * NHID]) : 0.f;
            }
            #pragma unroll
            for (int tt = 0; tt < SCH; tt++) {
                int t = c * SCH + tt;
                if (t < TT) {
                    float gv = bufA[tt];
                    ring[t & 127][tid] = gv;
                    float gd = (t >= TKLEN) ? ring[(t - TKLEN) & 127][tid] : 0.f;

                    float pa_o = pa, qa_o = qa, ra_o = ra;
                    pa = fmaf(D_SR, pa_o, gv);
                    pb = fmaf(D_SR, pb, D_SR * pa_o);
                    qa = fmaf(D_SR, qa_o, gd);
                    qb = fmaf(D_SR, qb, D_SR * qa_o);

                    float y = C_SR * (pb - E10 * fmaf(100.f, qa, qb));
                    float u = fmaf(C_REF, rb, y);
                    float sp = (u >= THETA) ? 1.f : 0.f;

                    ra = fmaf(D_REF, ra_o, sp);
                    rb = fmaf(D_REF, rb, D_REF * ra_o);

                    unsigned wbits = __ballot_sync(0xffffffffu, sp != 0.f);
                    if (lane == 0) sb[(size_t)t * NHG] = wbits;
                }
            }
        }
        // ---- odd chunk: compute from bufB, prefetch into bufA ----
        {
            const int tn0 = (c + 2) * SCH;
            #pragma unroll
            for (int tt = 0; tt < SCH; tt++) {
                int tn = tn0 + tt;
                bufA[tt] = (tn < TT) ? __ldg(&g[(size_t)tn * NHID]) : 0.f;
            }
            #pragma unroll
            for (int tt = 0; tt < SCH; tt++) {
                int t = (c + 1) * SCH + tt;
                if (t < TT) {
                    float gv = bufB[tt];
                    ring[t & 127][tid] = gv;
                    float gd = (t >= TKLEN) ? ring[(t - TKLEN) & 127][tid] : 0.f;

                    float pa_o = pa, qa_o = qa, ra_o = ra;
                    pa = fmaf(D_SR, pa_o, gv);
                    pb = fmaf(D_SR, pb, D_SR * pa_o);
                    qa = fmaf(D_SR, qa_o, gd);
                    qb = fmaf(D_SR, qb, D_SR * qa_o);

                    float y = C_SR * (pb - E10 * fmaf(100.f, qa, qb));
                    float u = fmaf(C_REF, rb, y);
                    float sp = (u >= THETA) ? 1.f : 0.f;

                    ra = fmaf(D_REF, ra_o, sp);
                    rb = fmaf(D_REF, rb, D_REF * ra_o);

                    unsigned wbits = __ballot_sync(0xffffffffu, sp != 0.f);
                    if (lane == 0) sb[(size_t)t * NHG] = wbits;
                }
            }
        }
    }
}

// ---------------------------------------------------------------------------
// GEMM2 (sparse): warp per (b,t). Spikes are exactly 1.0 -> G2[t][o] is a sum
// of W2^T rows over active h (ascending order). Lanes 0..9 hold outputs.
// ---------------------------------------------------------------------------
__global__ void __launch_bounds__(256) gemm2_kernel(const float* __restrict__ W2) {
    __shared__ float w2t[NHID * NOUT];   // transposed [h][o], 20 KB
    for (int i = threadIdx.x; i < NOUT * NHID; i += 256) {
        int o = i / NHID, h = i - o * NHID;
        w2t[h * NOUT + o] = W2[i];
    }
    __syncthreads();

    const int b = blockIdx.y;
    const int t = blockIdx.x * 8 + (threadIdx.x >> 5);
    const int lane = threadIdx.x & 31;
    if (t >= TT) return;

    const unsigned* srow = g_S1b + ((size_t)b * TT + t) * NHG;
    unsigned mw = (lane < NHG) ? srow[lane] : 0u;

    float acc = 0.f;   // lane<10: accumulator for o=lane
    unsigned act = __ballot_sync(0xffffffffu, mw != 0u);
    while (act) {
        int j = __ffs(act) - 1;
        act &= act - 1;
        unsigned w = __shfl_sync(0xffffffffu, mw, j);
        int hbase = j * 32;
        while (w) {
            int bit = __ffs(w) - 1;
            w &= w - 1;
            if (lane < NOUT) acc += w2t[(hbase + bit) * NOUT + lane];
        }
    }
    if (lane < NOUT)
        g_G2[((size_t)b * TT + t) * NOUT + lane] = acc;
}

// ---------------------------------------------------------------------------
// scan2: block per b. Stage G2[b] into smem, 10 threads run the spike scan.
// ---------------------------------------------------------------------------
__global__ void __launch_bounds__(128) scan2_kernel(float* __restrict__ out) {
    __shared__ float g2s[TT * NOUT];
    const int b = blockIdx.x;

    const float* src = g_G2 + (size_t)b * TT * NOUT;
    for (int i = threadIdx.x; i < TT * NOUT; i += 128) g2s[i] = src[i];
    __syncthreads();

    if (threadIdx.x < NOUT) {
        const int o = threadIdx.x;
        float* y_out = out + ((size_t)b * NOUT + o) * TT;

        float pa = 0.f, pb = 0.f, qa = 0.f, qb = 0.f, ra = 0.f, rb = 0.f;
        for (int t = 0; t < TT; t++) {
            float gv = g2s[t * NOUT + o];
            float gd = (t >= TKLEN) ? g2s[(t - TKLEN) * NOUT + o] : 0.f;

            float pa_o = pa, qa_o = qa, ra_o = ra;
            pa = fmaf(D_SR, pa_o, gv);
            pb = fmaf(D_SR, pb, D_SR * pa_o);
            qa = fmaf(D_SR, qa_o, gd);
            qb = fmaf(D_SR, qb, D_SR * qa_o);

            float y = C_SR * (pb - E10 * fmaf(100.f, qa, qb));
            float u = fmaf(C_REF, rb, y);
            float sp = (u >= THETA) ? 1.f : 0.f;

            ra = fmaf(D_REF, ra_o, sp);
            rb = fmaf(D_REF, rb, D_REF * ra_o);

            y_out[t] = sp;
        }
    }
}

// ---------------------------------------------------------------------------
extern "C" void kernel_launch(void* const* d_in, const int* in_sizes, int n_in,
                              void* d_out, int out_size) {
    const float* X  = (const float*)d_in[0];   // [32][2312][350]
    const float* W1 = (const float*)d_in[1];   // [512][2312]
    const float* W2 = (const float*)d_in[2];   // [10][512]
    float* out = (float*)d_out;                // [32][10][350]

    dim3 gT((NIN + 31) / 32, NHID / 32);
    w1t_kernel<<<gT, 256>>>(W1);

    dim3 gM(NIG, BATCH);
    maskbuild_kernel<<<gM, 352>>>(X);

    dim3 gS((TT + 7) / 8, BATCH);
    spgemm1_kernel<<<gS, 256>>>();

    dim3 gScan(NHID / 128, BATCH);   // (4, 32) = 128 blocks
    scan1_kernel<<<gScan, 128>>>();

    dim3 gG2((TT + 7) / 8, BATCH);
    gemm2_kernel<<<gG2, 256>>>(W2);

    scan2_kernel<<<BATCH, 128>>>(out);
}

// round 7
// speedup vs baseline: 1.2456x; 1.2456x over previous
#include <cuda_runtime.h>

#define BATCH 32
#define NIN   2312
#define NHID  512
#define NOUT  10
#define TT    350
#define TKLEN 100
#define NIG   73    // ceil(NIN/32) mask words per (b,t)
#define NHG   (NHID/32)

#define THETA 10.0f
#define D_SR  0.90483741803595952f     // exp(-0.1)
#define C_SR  0.27182818284590452f     // e/10
#define E10   4.5399929762484854e-05f  // exp(-10)
#define D_REF 0.36787944117144233f     // exp(-1)
#define C_REF -54.365636569180902f     // -20e

// scratch (allocation-free: device globals)
__device__ float    g_W1T[(size_t)NIN * NHID];          // [i][h]
__device__ unsigned g_M  [(size_t)BATCH * TT * NIG];    // X bitmasks [b][t][ig]
__device__ float    g_G1 [(size_t)BATCH * TT * NHID];   // [b][t][h]
__device__ unsigned g_S1b[(size_t)BATCH * TT * NHG];    // s1 bitmasks [b][t][hg]
__device__ float    g_G2 [(size_t)BATCH * TT * NOUT];   // [b][t][o]

// ---------------------------------------------------------------------------
// Transpose W1 [NHID][NIN] -> W1T [NIN][NHID]
// ---------------------------------------------------------------------------
__global__ void __launch_bounds__(256) w1t_kernel(const float* __restrict__ W1) {
    __shared__ float tile[32][33];
    int i0 = blockIdx.x * 32;
    int h0 = blockIdx.y * 32;
    int lx = threadIdx.x & 31;
    int ly = threadIdx.x >> 5;

    #pragma unroll
    for (int r = 0; r < 4; r++) {
        int h = h0 + ly + r * 8;
        int i = i0 + lx;
        tile[ly + r * 8][lx] = (i < NIN) ? W1[(size_t)h * NIN + i] : 0.f;
    }
    __syncthreads();
    #pragma unroll
    for (int r = 0; r < 4; r++) {
        int i = i0 + ly + r * 8;
        int h = h0 + lx;
        if (i < NIN) g_W1T[(size_t)i * NHID + h] = tile[lx][ly + r * 8];
    }
}

// ---------------------------------------------------------------------------
// Mask build: block per (b, ig). Stage 32 rows of X coalescedly in smem,
// then thread t packs the 32-bit word -> g_M[b][t][ig].
// ---------------------------------------------------------------------------
__global__ void __launch_bounds__(352) maskbuild_kernel(const float* __restrict__ X) {
    __shared__ float xs[32][TT];
    const int ig = blockIdx.x;
    const int b  = blockIdx.y;
    const int tid = threadIdx.x;

    #pragma unroll 1
    for (int j = 0; j < 32; j++) {
        int i = ig * 32 + j;
        if (tid < TT)
            xs[j][tid] = (i < NIN) ? X[((size_t)b * NIN + i) * TT + tid] : 0.f;
    }
    __syncthreads();

    if (tid < TT) {
        unsigned w = 0;
        #pragma unroll
        for (int j = 0; j < 32; j++)
            if (xs[j][tid] != 0.f) w |= 1u << j;
        g_M[((size_t)b * TT + tid) * NIG + ig] = w;
    }
}

// ---------------------------------------------------------------------------
// Sparse GEMM1 v2: 1024-thread blocks = 32 warps = 32 consecutive t of one b,
// sweeping the i-axis in LOCKSTEP (syncthreads per 32-word chunk) so W1T rows
// hit L1 across the 32 t's (~79% hit rate -> ~0.56 GB L2 traffic).
// Inner gather identical to round 4: ascending-i, deterministic order.
// ---------------------------------------------------------------------------
__device__ __forceinline__ void add4(float4& a, const float4& r) {
    a.x += r.x; a.y += r.y; a.z += r.z; a.w += r.w;
}

__global__ void __launch_bounds__(1024) spgemm1_kernel() {
    const int warp = threadIdx.x >> 5;
    const int lane = threadIdx.x & 31;
    const int b = blockIdx.y;
    const int t = blockIdx.x * 32 + warp;
    const bool live = (t < TT);

    const unsigned* __restrict__ mrow =
        g_M + ((size_t)b * TT + (live ? t : 0)) * NIG;

    float4 acc0 = make_float4(0.f, 0.f, 0.f, 0.f);
    float4 acc1 = acc0, acc2 = acc0, acc3 = acc0;

    #pragma unroll
    for (int cb = 0; cb < 96; cb += 32) {
        unsigned mw = (live && (cb + lane < NIG)) ? mrow[cb + lane] : 0u;
        unsigned act = __ballot_sync(0xffffffffu, mw != 0u);
        while (act) {
            int j = __ffs(act) - 1;
            act &= act - 1;
            unsigned w = __shfl_sync(0xffffffffu, mw, j);
            int ibase = (cb + j) * 32;
            while (w) {
                int bit = __ffs(w) - 1;
                w &= w - 1;
                const float4* row = (const float4*)(g_W1T + (size_t)(ibase + bit) * NHID);
                float4 r0 = row[lane];
                float4 r1 = row[lane + 32];
                float4 r2 = row[lane + 64];
                float4 r3 = row[lane + 96];
                add4(acc0, r0); add4(acc1, r1); add4(acc2, r2); add4(acc3, r3);
            }
        }
        __syncthreads();   // keep the 32 t-warps in step -> L1 temporal reuse
    }

    if (live) {
        float4* out = (float4*)(g_G1 + ((size_t)b * TT + t) * NHID);
        out[lane]      = acc0;
        out[lane + 32] = acc1;
        out[lane + 64] = acc2;
        out[lane + 96] = acc3;
    }
}

// ---------------------------------------------------------------------------
// scan1 v4: block = (b, 128-h slice), one channel per thread. NO smem.
// Both streams (gv = g[t], gd = g[t-100]) are double-buffered register
// prefetches from global (addresses known in advance). 14 chunks of 25.
// Per-channel arithmetic identical to all prior rounds.
// ---------------------------------------------------------------------------
#define SCH 25   // 14 * 25 = 350 exactly

#define SCAN1_STEP(GV, GD)                                     \
    {                                                          \
        float gv = (GV), gd = (GD);                            \
        float pa_o = pa, qa_o = qa, ra_o = ra;                 \
        pa = fmaf(D_SR, pa_o, gv);                             \
        pb = fmaf(D_SR, pb, D_SR * pa_o);                      \
        qa = fmaf(D_SR, qa_o, gd);                             \
        qb = fmaf(D_SR, qb, D_SR * qa_o);                      \
        float y = C_SR * (pb - E10 * fmaf(100.f, qa, qb));     \
        float u = fmaf(C_REF, rb, y);                          \
        float sp = (u >= THETA) ? 1.f : 0.f;                   \
        ra = fmaf(D_REF, ra_o, sp);                            \
        rb = fmaf(D_REF, rb, D_REF * ra_o);                    \
        unsigned wbits = __ballot_sync(0xffffffffu, sp != 0.f);\
        if (lane == 0) sb[(size_t)t * NHG] = wbits;            \
    }

__global__ void __launch_bounds__(128) scan1_kernel() {
    const int b   = blockIdx.y;
    const int h0  = blockIdx.x * 128;
    const int tid = threadIdx.x;
    const int lane = tid & 31;
    const int hg  = (h0 + tid) >> 5;

    const float* __restrict__ g = g_G1 + (size_t)b * TT * NHID + h0 + tid;
    unsigned* __restrict__ sb = g_S1b + (size_t)b * TT * NHG + hg;

    float pa = 0.f, pb = 0.f;
    float qa = 0.f, qb = 0.f;
    float ra = 0.f, rb = 0.f;

    float va[SCH], vb[SCH], da[SCH], db[SCH];

    // preload chunk 0 (t = 0..24; gd all zero there)
    #pragma unroll
    for (int i = 0; i < SCH; i++) {
        va[i] = __ldg(&g[(size_t)i * NHID]);
        da[i] = 0.f;
    }

    #pragma unroll 1
    for (int c = 0; c < 14; c += 2) {
        // prefetch chunk c+1 into vb/db
        #pragma unroll
        for (int i = 0; i < SCH; i++) {
            int tn = (c + 1) * SCH + i;
            vb[i] = __ldg(&g[(size_t)tn * NHID]);
            db[i] = (tn >= TKLEN) ? __ldg(&g[(size_t)(tn - TKLEN) * NHID]) : 0.f;
        }
        // compute chunk c from va/da
        #pragma unroll
        for (int i = 0; i < SCH; i++) {
            int t = c * SCH + i;
            SCAN1_STEP(va[i], da[i]);
        }
        // prefetch chunk c+2 into va/da (skip on last pair)
        if (c + 2 < 14) {
            #pragma unroll
            for (int i = 0; i < SCH; i++) {
                int tn = (c + 2) * SCH + i;
                va[i] = __ldg(&g[(size_t)tn * NHID]);
                da[i] = (tn >= TKLEN) ? __ldg(&g[(size_t)(tn - TKLEN) * NHID]) : 0.f;
            }
        }
        // compute chunk c+1 from vb/db
        #pragma unroll
        for (int i = 0; i < SCH; i++) {
            int t = (c + 1) * SCH + i;
            SCAN1_STEP(vb[i], db[i]);
        }
    }
}

// ---------------------------------------------------------------------------
// GEMM2 (sparse): warp per (b,t). Spikes are exactly 1.0 -> G2[t][o] is a sum
// of W2^T rows over active h (ascending order). Lanes 0..9 hold outputs.
// ---------------------------------------------------------------------------
__global__ void __launch_bounds__(256) gemm2_kernel(const float* __restrict__ W2) {
    __shared__ float w2t[NHID * NOUT];   // transposed [h][o], 20 KB
    for (int i = threadIdx.x; i < NOUT * NHID; i += 256) {
        int o = i / NHID, h = i - o * NHID;
        w2t[h * NOUT + o] = W2[i];
    }
    __syncthreads();

    const int b = blockIdx.y;
    const int t = blockIdx.x * 8 + (threadIdx.x >> 5);
    const int lane = threadIdx.x & 31;
    if (t >= TT) return;

    const unsigned* srow = g_S1b + ((size_t)b * TT + t) * NHG;
    unsigned mw = (lane < NHG) ? srow[lane] : 0u;

    float acc = 0.f;   // lane<10: accumulator for o=lane
    unsigned act = __ballot_sync(0xffffffffu, mw != 0u);
    while (act) {
        int j = __ffs(act) - 1;
        act &= act - 1;
        unsigned w = __shfl_sync(0xffffffffu, mw, j);
        int hbase = j * 32;
        while (w) {
            int bit = __ffs(w) - 1;
            w &= w - 1;
            if (lane < NOUT) acc += w2t[(hbase + bit) * NOUT + lane];
        }
    }
    if (lane < NOUT)
        g_G2[((size_t)b * TT + t) * NOUT + lane] = acc;
}

// ---------------------------------------------------------------------------
// scan2: block per b. Stage G2[b] into smem, 10 threads run the spike scan.
// ---------------------------------------------------------------------------
__global__ void __launch_bounds__(128) scan2_kernel(float* __restrict__ out) {
    __shared__ float g2s[TT * NOUT];
    const int b = blockIdx.x;

    const float* src = g_G2 + (size_t)b * TT * NOUT;
    for (int i = threadIdx.x; i < TT * NOUT; i += 128) g2s[i] = src[i];
    __syncthreads();

    if (threadIdx.x < NOUT) {
        const int o = threadIdx.x;
        float* y_out = out + ((size_t)b * NOUT + o) * TT;

        float pa = 0.f, pb = 0.f, qa = 0.f, qb = 0.f, ra = 0.f, rb = 0.f;
        for (int t = 0; t < TT; t++) {
            float gv = g2s[t * NOUT + o];
            float gd = (t >= TKLEN) ? g2s[(t - TKLEN) * NOUT + o] : 0.f;

            float pa_o = pa, qa_o = qa, ra_o = ra;
            pa = fmaf(D_SR, pa_o, gv);
            pb = fmaf(D_SR, pb, D_SR * pa_o);
            qa = fmaf(D_SR, qa_o, gd);
            qb = fmaf(D_SR, qb, D_SR * qa_o);

            float y = C_SR * (pb - E10 * fmaf(100.f, qa, qb));
            float u = fmaf(C_REF, rb, y);
            float sp = (u >= THETA) ? 1.f : 0.f;

            ra = fmaf(D_REF, ra_o, sp);
            rb = fmaf(D_REF, rb, D_REF * ra_o);

            y_out[t] = sp;
        }
    }
}

// ---------------------------------------------------------------------------
extern "C" void kernel_launch(void* const* d_in, const int* in_sizes, int n_in,
                              void* d_out, int out_size) {
    const float* X  = (const float*)d_in[0];   // [32][2312][350]
    const float* W1 = (const float*)d_in[1];   // [512][2312]
    const float* W2 = (const float*)d_in[2];   // [10][512]
    float* out = (float*)d_out;                // [32][10][350]

    dim3 gT((NIN + 31) / 32, NHID / 32);
    w1t_kernel<<<gT, 256>>>(W1);

    dim3 gM(NIG, BATCH);
    maskbuild_kernel<<<gM, 352>>>(X);

    dim3 gS((TT + 31) / 32, BATCH);   // (11, 32) blocks of 1024 threads
    spgemm1_kernel<<<gS, 1024>>>();

    dim3 gScan(NHID / 128, BATCH);    // (4, 32) = 128 blocks
    scan1_kernel<<<gScan, 128>>>();

    dim3 gG2((TT + 7) / 8, BATCH);
    gemm2_kernel<<<gG2, 256>>>(W2);

    scan2_kernel<<<BATCH, 128>>>(out);
}

// round 8
// speedup vs baseline: 1.4528x; 1.1663x over previous
#include <cuda_runtime.h>

#define BATCH 32
#define NIN   2312
#define NHID  512
#define NOUT  10
#define TT    350
#define TKLEN 100
#define NIG   73    // ceil(NIN/32) mask words per (b,t)
#define NHG   (NHID/32)

#define THETA 10.0f
#define D_SR  0.90483741803595952f     // exp(-0.1)
#define C_SR  0.27182818284590452f     // e/10
#define E10   4.5399929762484854e-05f  // exp(-10)
#define D_REF 0.36787944117144233f     // exp(-1)
#define C_REF -54.365636569180902f     // -20e

// scratch (allocation-free: device globals)
__device__ float    g_W1T[(size_t)NIN * NHID];          // [i][h]
__device__ unsigned g_M  [(size_t)BATCH * TT * NIG];    // X bitmasks [b][t][ig]
__device__ float    g_G1 [(size_t)BATCH * TT * NHID];   // [b][t][h]
__device__ unsigned g_S1b[(size_t)BATCH * TT * NHG];    // s1 bitmasks [b][t][hg]
__device__ float    g_G2 [(size_t)BATCH * TT * NOUT];   // [b][t][o]

// ---------------------------------------------------------------------------
// Transpose W1 [NHID][NIN] -> W1T [NIN][NHID]
// ---------------------------------------------------------------------------
__global__ void __launch_bounds__(256) w1t_kernel(const float* __restrict__ W1) {
    __shared__ float tile[32][33];
    int i0 = blockIdx.x * 32;
    int h0 = blockIdx.y * 32;
    int lx = threadIdx.x & 31;
    int ly = threadIdx.x >> 5;

    #pragma unroll
    for (int r = 0; r < 4; r++) {
        int h = h0 + ly + r * 8;
        int i = i0 + lx;
        tile[ly + r * 8][lx] = (i < NIN) ? W1[(size_t)h * NIN + i] : 0.f;
    }
    __syncthreads();
    #pragma unroll
    for (int r = 0; r < 4; r++) {
        int i = i0 + ly + r * 8;
        int h = h0 + lx;
        if (i < NIN) g_W1T[(size_t)i * NHID + h] = tile[lx][ly + r * 8];
    }
}

// ---------------------------------------------------------------------------
// Mask build: block per (b, ig). Stage 32 rows of X coalescedly in smem,
// then thread t packs the 32-bit word -> g_M[b][t][ig].
// ---------------------------------------------------------------------------
__global__ void __launch_bounds__(352) maskbuild_kernel(const float* __restrict__ X) {
    __shared__ float xs[32][TT];
    const int ig = blockIdx.x;
    const int b  = blockIdx.y;
    const int tid = threadIdx.x;

    #pragma unroll 1
    for (int j = 0; j < 32; j++) {
        int i = ig * 32 + j;
        if (tid < TT)
            xs[j][tid] = (i < NIN) ? X[((size_t)b * NIN + i) * TT + tid] : 0.f;
    }
    __syncthreads();

    if (tid < TT) {
        unsigned w = 0;
        #pragma unroll
        for (int j = 0; j < 32; j++)
            if (xs[j][tid] != 0.f) w |= 1u << j;
        g_M[((size_t)b * TT + tid) * NIG + ig] = w;
    }
}

// ---------------------------------------------------------------------------
// Sparse GEMM1 (round-4 proven version): warp per (b,t); 8 consecutive t per
// block (incidental L1 row reuse ~50%, near structural ceiling).
// Gathers active W1T rows in ascending-i order (deterministic).
// ---------------------------------------------------------------------------
__device__ __forceinline__ void add4(float4& a, const float4& r) {
    a.x += r.x; a.y += r.y; a.z += r.z; a.w += r.w;
}

__global__ void __launch_bounds__(256) spgemm1_kernel() {
    const int warp = threadIdx.x >> 5;
    const int lane = threadIdx.x & 31;
    const int b = blockIdx.y;
    const int t = blockIdx.x * 8 + warp;
    if (t >= TT) return;

    const unsigned* __restrict__ mrow = g_M + ((size_t)b * TT + t) * NIG;

    float4 acc0 = make_float4(0.f, 0.f, 0.f, 0.f);
    float4 acc1 = acc0, acc2 = acc0, acc3 = acc0;

    #pragma unroll
    for (int cb = 0; cb < 96; cb += 32) {
        unsigned mw = (cb + lane < NIG) ? mrow[cb + lane] : 0u;
        unsigned act = __ballot_sync(0xffffffffu, mw != 0u);
        while (act) {
            int j = __ffs(act) - 1;
            act &= act - 1;
            unsigned w = __shfl_sync(0xffffffffu, mw, j);
            int ibase = (cb + j) * 32;
            while (w) {
                int bit = __ffs(w) - 1;
                w &= w - 1;
                const float4* row = (const float4*)(g_W1T + (size_t)(ibase + bit) * NHID);
                float4 r0 = row[lane];
                float4 r1 = row[lane + 32];
                float4 r2 = row[lane + 64];
                float4 r3 = row[lane + 96];
                add4(acc0, r0); add4(acc1, r1); add4(acc2, r2); add4(acc3, r3);
            }
        }
    }

    float4* out = (float4*)(g_G1 + ((size_t)b * TT + t) * NHID);
    out[lane]      = acc0;
    out[lane + 32] = acc1;
    out[lane + 64] = acc2;
    out[lane + 96] = acc3;
}

// ---------------------------------------------------------------------------
// scan1 v5: block = (b, 128-h slice), one channel per thread. NO smem.
// Single load stream: gd[t] = gv[t-100] comes from a 6-buffer register ring
// (chunk length 25, 100 = exactly 4 chunks back). Fully unrolled schedule:
// prefetch chunk c+1 while computing chunk c. Arithmetic order identical.
// ---------------------------------------------------------------------------
#define SCH 25   // 14 * 25 = 350 exactly

#define SCAN1_STEP(T, GV, GD)                                  \
    {                                                          \
        const int t = (T);                                     \
        float gv = (GV), gd = (GD);                            \
        float pa_o = pa, qa_o = qa, ra_o = ra;                 \
        pa = fmaf(D_SR, pa_o, gv);                             \
        pb = fmaf(D_SR, pb, D_SR * pa_o);                      \
        qa = fmaf(D_SR, qa_o, gd);                             \
        qb = fmaf(D_SR, qb, D_SR * qa_o);                      \
        float y = C_SR * (pb - E10 * fmaf(100.f, qa, qb));     \
        float u = fmaf(C_REF, rb, y);                          \
        float sp = (u >= THETA) ? 1.f : 0.f;                   \
        ra = fmaf(D_REF, ra_o, sp);                            \
        rb = fmaf(D_REF, rb, D_REF * ra_o);                    \
        unsigned wbits = __ballot_sync(0xffffffffu, sp != 0.f);\
        if (lane == 0) sb[(size_t)t * NHG] = wbits;            \
    }

// prefetch chunk CC into buffer B
#define PF(CC, B)                                              \
    _Pragma("unroll")                                          \
    for (int i = 0; i < SCH; i++)                              \
        B[i] = __ldg(&g[(size_t)((CC) * SCH + i) * NHID]);

// compute chunk CC, gv from BV, gd from BD (chunk CC-4)
#define CK(CC, BV, BD)                                         \
    _Pragma("unroll")                                          \
    for (int i = 0; i < SCH; i++)                              \
        SCAN1_STEP((CC) * SCH + i, BV[i], BD[i])

// compute chunk CC with gd == 0 (t < 100)
#define CK0(CC, BV)                                            \
    _Pragma("unroll")                                          \
    for (int i = 0; i < SCH; i++)                              \
        SCAN1_STEP((CC) * SCH + i, BV[i], 0.f)

__global__ void __launch_bounds__(128) scan1_kernel() {
    const int b   = blockIdx.y;
    const int h0  = blockIdx.x * 128;
    const int tid = threadIdx.x;
    const int lane = tid & 31;
    const int hg  = (h0 + tid) >> 5;

    const float* __restrict__ g = g_G1 + (size_t)b * TT * NHID + h0 + tid;
    unsigned* __restrict__ sb = g_S1b + (size_t)b * TT * NHG + hg;

    float pa = 0.f, pb = 0.f;
    float qa = 0.f, qb = 0.f;
    float ra = 0.f, rb = 0.f;

    float b0[SCH], b1[SCH], b2[SCH], b3[SCH], b4[SCH], b5[SCH];

    PF(0, b0)
    PF(1, b1)  CK0(0, b0)
    PF(2, b2)  CK0(1, b1)
    PF(3, b3)  CK0(2, b2)
    PF(4, b4)  CK0(3, b3)
    PF(5, b5)  CK(4, b4, b0)
    PF(6, b0)  CK(5, b5, b1)
    PF(7, b1)  CK(6, b0, b2)
    PF(8, b2)  CK(7, b1, b3)
    PF(9, b3)  CK(8, b2, b4)
    PF(10, b4) CK(9, b3, b5)
    PF(11, b5) CK(10, b4, b0)
    PF(12, b0) CK(11, b5, b1)
    PF(13, b1) CK(12, b0, b2)
               CK(13, b1, b3)
}

// ---------------------------------------------------------------------------
// GEMM2 (sparse): warp per (b,t). Spikes are exactly 1.0 -> G2[t][o] is a sum
// of W2^T rows over active h (ascending order). Lanes 0..9 hold outputs.
// ---------------------------------------------------------------------------
__global__ void __launch_bounds__(256) gemm2_kernel(const float* __restrict__ W2) {
    __shared__ float w2t[NHID * NOUT];   // transposed [h][o], 20 KB
    for (int i = threadIdx.x; i < NOUT * NHID; i += 256) {
        int o = i / NHID, h = i - o * NHID;
        w2t[h * NOUT + o] = W2[i];
    }
    __syncthreads();

    const int b = blockIdx.y;
    const int t = blockIdx.x * 8 + (threadIdx.x >> 5);
    const int lane = threadIdx.x & 31;
    if (t >= TT) return;

    const unsigned* srow = g_S1b + ((size_t)b * TT + t) * NHG;
    unsigned mw = (lane < NHG) ? srow[lane] : 0u;

    float acc = 0.f;   // lane<10: accumulator for o=lane
    unsigned act = __ballot_sync(0xffffffffu, mw != 0u);
    while (act) {
        int j = __ffs(act) - 1;
        act &= act - 1;
        unsigned w = __shfl_sync(0xffffffffu, mw, j);
        int hbase = j * 32;
        while (w) {
            int bit = __ffs(w) - 1;
            w &= w - 1;
            if (lane < NOUT) acc += w2t[(hbase + bit) * NOUT + lane];
        }
    }
    if (lane < NOUT)
        g_G2[((size_t)b * TT + t) * NOUT + lane] = acc;
}

// ---------------------------------------------------------------------------
// scan2: block per b. Stage G2[b] into smem, 10 threads run the spike scan.
// ---------------------------------------------------------------------------
__global__ void __launch_bounds__(128) scan2_kernel(float* __restrict__ out) {
    __shared__ float g2s[TT * NOUT];
    const int b = blockIdx.x;

    const float* src = g_G2 + (size_t)b * TT * NOUT;
    for (int i = threadIdx.x; i < TT * NOUT; i += 128) g2s[i] = src[i];
    __syncthreads();

    if (threadIdx.x < NOUT) {
        const int o = threadIdx.x;
        float* y_out = out + ((size_t)b * NOUT + o) * TT;

        float pa = 0.f, pb = 0.f, qa = 0.f, qb = 0.f, ra = 0.f, rb = 0.f;
        for (int t = 0; t < TT; t++) {
            float gv = g2s[t * NOUT + o];
            float gd = (t >= TKLEN) ? g2s[(t - TKLEN) * NOUT + o] : 0.f;

            float pa_o = pa, qa_o = qa, ra_o = ra;
            pa = fmaf(D_SR, pa_o, gv);
            pb = fmaf(D_SR, pb, D_SR * pa_o);
            qa = fmaf(D_SR, qa_o, gd);
            qb = fmaf(D_SR, qb, D_SR * qa_o);

            float y = C_SR * (pb - E10 * fmaf(100.f, qa, qb));
            float u = fmaf(C_REF, rb, y);
            float sp = (u >= THETA) ? 1.f : 0.f;

            ra = fmaf(D_REF, ra_o, sp);
            rb = fmaf(D_REF, rb, D_REF * ra_o);

            y_out[t] = sp;
        }
    }
}

// ---------------------------------------------------------------------------
extern "C" void kernel_launch(void* const* d_in, const int* in_sizes, int n_in,
                              void* d_out, int out_size) {
    const float* X  = (const float*)d_in[0];   // [32][2312][350]
    const float* W1 = (const float*)d_in[1];   // [512][2312]
    const float* W2 = (const float*)d_in[2];   // [10][512]
    float* out = (float*)d_out;                // [32][10][350]

    dim3 gT((NIN + 31) / 32, NHID / 32);
    w1t_kernel<<<gT, 256>>>(W1);

    dim3 gM(NIG, BATCH);
    maskbuild_kernel<<<gM, 352>>>(X);

    dim3 gS((TT + 7) / 8, BATCH);
    spgemm1_kernel<<<gS, 256>>>();

    dim3 gScan(NHID / 128, BATCH);    // (4, 32) = 128 blocks
    scan1_kernel<<<gScan, 128>>>();

    dim3 gG2((TT + 7) / 8, BATCH);
    gemm2_kernel<<<gG2, 256>>>(W2);

    scan2_kernel<<<BATCH, 128>>>(out);
}